// round 15
// baseline (speedup 1.0000x reference)
#include <cuda_runtime.h>
#include <cuda_bf16.h>
#include <stdint.h>

#define BN_EPS 1e-5f
#define KTOT 528
#define NSTG 33   // KTOT / 16

// ------------- device scratch (no allocations allowed) -------------
__device__ float g_hA[2][KTOT * 2048];   // A operand, transposed [k][b]; rows 0..511 = h, 512..527 = hrelu
__device__ float g_c[512 * 2048];        // cell state transposed [j][b]
__device__ float g_lp[2][2048 * 2];
__device__ float g_Beff[KTOT * 2048];    // fused, tf32-rounded, cols n' = 4j+q
__device__ float g_cb[2048];             // fused gate bias
__device__ float g_A1[32];               // folded se layer1 weights [2][16]
__device__ float g_B1[16];
__device__ float g_hpw1f[8192];          // folded hp layer1 [512][16]
__device__ float g_hpb1f[16];

// ------------- helpers -------------
__device__ __forceinline__ float tf32rf(float x) {
    uint32_t u; asm("cvt.rna.tf32.f32 %0, %1;" : "=r"(u) : "f"(x));
    return __uint_as_float(u);
}
__device__ __forceinline__ uint32_t f2tf(float x) {
    uint32_t u; asm("cvt.rna.tf32.f32 %0, %1;" : "=r"(u) : "f"(x));
    return u;
}
__device__ __forceinline__ float sigf(float x) { return 1.f / (1.f + __expf(-x)); }

__device__ __forceinline__ void cp16(void* s, const void* g) {
    uint32_t sa = (uint32_t)__cvta_generic_to_shared(s);
    asm volatile("cp.async.cg.shared.global [%0], [%1], 16;\n" :: "r"(sa), "l"(g) : "memory");
}
__device__ __forceinline__ void mma8(float* c, const uint32_t* a, const uint32_t* b) {
    asm volatile(
        "mma.sync.aligned.m16n8k8.row.col.f32.tf32.tf32.f32 "
        "{%0,%1,%2,%3},{%4,%5,%6,%7},{%8,%9},{%0,%1,%2,%3};\n"
        : "+f"(c[0]), "+f"(c[1]), "+f"(c[2]), "+f"(c[3])
        : "r"(a[0]), "r"(a[1]), "r"(a[2]), "r"(a[3]), "r"(b[0]), "r"(b[1]));
}

// ------------- prep kernels (run once per launch, deterministic) -------------
__global__ void prep_fold(const float* se_w1, const float* se_b1, const float* se_g,
                          const float* se_bt, const float* se_m, const float* se_v,
                          const float* hp_w1, const float* hp_b1, const float* hp_g,
                          const float* hp_bt, const float* hp_m, const float* hp_v) {
    __shared__ float s2s[16];
    int t = threadIdx.x;
    if (t < 16) {
        float s = se_g[t] * rsqrtf(se_v[t] + BN_EPS);
        g_A1[t]      = se_w1[t] * s;
        g_A1[16 + t] = se_w1[16 + t] * s;
        g_B1[t]      = (se_b1[t] - se_m[t]) * s + se_bt[t];
        float s2 = hp_g[t] * rsqrtf(hp_v[t] + BN_EPS);
        s2s[t] = s2;
        g_hpb1f[t] = (hp_b1[t] - hp_m[t]) * s2 + hp_bt[t];
    }
    __syncthreads();
    for (int i = t; i < 8192; i += 256) g_hpw1f[i] = hp_w1[i] * s2s[i & 15];
}

// Beff rows 0..511: interleaved w_hh transpose
__global__ void prep_whh(const float* __restrict__ w_hh) {
    int id = blockIdx.x * 256 + threadIdx.x;          // 1048576 threads
    int np = id & 2047, k = id >> 11;
    int j = np >> 2, q = np & 3;
    g_Beff[k * 2048 + np] = tf32rf(w_hh[(q * 512 + j) * 512 + k]);
}

// Beff rows 512..527: Wse[jj][n] = sum_e se_w2[jj][e] * w_ih[n][e]
__global__ void prep_wse(const float* __restrict__ se_w2, const float* __restrict__ w_ih) {
    int id = blockIdx.x * 256 + threadIdx.x;          // 32768 threads
    int jj = id & 15, np = id >> 4;
    int j = np >> 2, q = np & 3;
    const float4* wr = (const float4*)(w_ih + (size_t)(q * 512 + j) * 512);
    const float4* sw = (const float4*)(se_w2 + (size_t)jj * 512);
    float acc = 0.f;
#pragma unroll 4
    for (int e = 0; e < 128; e++) {
        float4 a = wr[e], b = sw[e];
        acc += a.x * b.x + a.y * b.y + a.z * b.z + a.w * b.w;
    }
    g_Beff[(512 + jj) * 2048 + np] = tf32rf(acc);
}

// fused bias cb[n'] = b_ih[n] + b_hh[n] + se_b2 . w_ih[n]
__global__ void prep_cb(const float* __restrict__ se_b2, const float* __restrict__ w_ih,
                        const float* __restrict__ b_ih, const float* __restrict__ b_hh) {
    int np = blockIdx.x * 256 + threadIdx.x;          // 2048 threads
    int j = np >> 2, q = np & 3;
    int n = q * 512 + j;
    const float4* wr = (const float4*)(w_ih + (size_t)n * 512);
    const float4* sb = (const float4*)se_b2;
    float acc = b_ih[n] + b_hh[n];
#pragma unroll 4
    for (int e = 0; e < 128; e++) {
        float4 a = wr[e], b = sb[e];
        acc += a.x * b.x + a.y * b.y + a.z * b.z + a.w * b.w;
    }
    g_cb[np] = acc;
}

// transpose h0 -> g_hA[0], c0 -> g_c
__global__ void init_hc(const float* __restrict__ hh, const float* __restrict__ ch) {
    int id = blockIdx.x * 256 + threadIdx.x;          // 2097152 threads
    if (id < 1048576) {
        int b = id & 2047, j = id >> 11;
        g_hA[0][j * 2048 + b] = hh[b * 512 + j];
    } else {
        int k = id - 1048576;
        int b = k & 2047, j = k >> 11;
        g_c[j * 2048 + b] = ch[b * 512 + j];
    }
}

// lp0 copy + hrelu(lp0) into g_hA[0] rows 512..527  (needs prep_fold first)
__global__ void init_front(const float* __restrict__ last_pos) {
    int b = blockIdx.x * 256 + threadIdx.x;           // 2048 threads
    float l0 = last_pos[b * 2], l1 = last_pos[b * 2 + 1];
    g_lp[0][b * 2] = l0; g_lp[0][b * 2 + 1] = l1;
#pragma unroll
    for (int jj = 0; jj < 16; jj++)
        g_hA[0][(512 + jj) * 2048 + b] =
            fmaxf(l0 * g_A1[jj] + l1 * g_A1[16 + jj] + g_B1[jj], 0.f);
}

// ------------- per-step GEMM + fused LSTM cell -------------
// gates[b][n'] = sum_k A[k][b] * Beff[k][n'] + cb[n']; in-register i,f,g,o combine via lane^1 shfl.
__global__ void __launch_bounds__(256, 2) gemm_lstm(int cur) {
    __shared__ __align__(16) float As[2][16][132];
    __shared__ __align__(16) float Bs[2][16][132];
    const float* Ag = g_hA[cur];
    float* Hn = g_hA[cur ^ 1];
    int tid = threadIdx.x;
    int bm = blockIdx.y * 128, bn = blockIdx.x * 128;
    int lane = tid & 31, wid = tid >> 5;
    int wm = wid & 3, wn = wid >> 2;      // 4 warps in M (32 rows), 2 in N (64 cols)
    int tig = lane & 3, grp = lane >> 2;

    float acc[2][8][4];
#pragma unroll
    for (int a = 0; a < 2; a++)
#pragma unroll
        for (int b = 0; b < 8; b++)
#pragma unroll
            for (int c = 0; c < 4; c++) acc[a][b][c] = 0.f;

    auto load = [&](int st, int buf) {
        int k0 = st * 16;
#pragma unroll
        for (int i = 0; i < 2; i++) {
            int c = tid + i * 256;
            int row = c >> 5, ch = c & 31;
            cp16(&As[buf][row][ch * 4], Ag + (size_t)(k0 + row) * 2048 + bm + ch * 4);
            cp16(&Bs[buf][row][ch * 4], g_Beff + (size_t)(k0 + row) * 2048 + bn + ch * 4);
        }
    };

    load(0, 0);
    asm volatile("cp.async.commit_group;\n" ::: "memory");
    int buf = 0;
    for (int st = 0; st < NSTG; st++) {
        if (st + 1 < NSTG) load(st + 1, buf ^ 1);
        asm volatile("cp.async.commit_group;\n" ::: "memory");
        asm volatile("cp.async.wait_group 1;\n" ::: "memory");
        __syncthreads();
#pragma unroll
        for (int k8 = 0; k8 < 16; k8 += 8) {
            uint32_t af[2][4], bf[8][2];
#pragma unroll
            for (int mt = 0; mt < 2; mt++) {
                int m0 = wm * 32 + mt * 16 + grp;
                af[mt][0] = f2tf(As[buf][k8 + tig][m0]);
                af[mt][1] = f2tf(As[buf][k8 + tig][m0 + 8]);
                af[mt][2] = f2tf(As[buf][k8 + tig + 4][m0]);
                af[mt][3] = f2tf(As[buf][k8 + tig + 4][m0 + 8]);
            }
#pragma unroll
            for (int nt = 0; nt < 8; nt++) {
                int n0 = wn * 64 + nt * 8 + grp;
                bf[nt][0] = __float_as_uint(Bs[buf][k8 + tig][n0]);
                bf[nt][1] = __float_as_uint(Bs[buf][k8 + tig + 4][n0]);
            }
#pragma unroll
            for (int mt = 0; mt < 2; mt++)
#pragma unroll
                for (int nt = 0; nt < 8; nt++) mma8(acc[mt][nt], af[mt], bf[nt]);
        }
        __syncthreads();
        buf ^= 1;
    }

    // epilogue: lane pairs hold (i,f) / (g,o) of the same unit j
#pragma unroll
    for (int mt = 0; mt < 2; mt++) {
        int r0 = bm + wm * 32 + mt * 16 + grp;
#pragma unroll
        for (int nt = 0; nt < 8; nt++) {
            int col = bn + wn * 64 + nt * 8 + 2 * tig;
            float cb0 = g_cb[col], cb1 = g_cb[col + 1];
            float c0 = acc[mt][nt][0] + cb0;
            float c1 = acc[mt][nt][1] + cb1;
            float c2 = acc[mt][nt][2] + cb0;
            float c3 = acc[mt][nt][3] + cb1;
            float p0 = __shfl_xor_sync(0xffffffffu, c0, 1);
            float p1 = __shfl_xor_sync(0xffffffffu, c1, 1);
            float p2 = __shfl_xor_sync(0xffffffffu, c2, 1);
            float p3 = __shfl_xor_sync(0xffffffffu, c3, 1);
            if (!(lane & 1)) {                 // even lane: owns (i,f), partner sent (g,o)
                int j = col >> 2;
                float i0 = sigf(c0), f0 = sigf(c1), g0 = tanhf(p0), o0 = sigf(p1);
                float cc = g_c[j * 2048 + r0];
                cc = f0 * cc + i0 * g0;
                g_c[j * 2048 + r0] = cc;
                Hn[j * 2048 + r0] = o0 * tanhf(cc);
                float i1 = sigf(c2), f1 = sigf(c3), g1 = tanhf(p2), o1 = sigf(p3);
                float cd = g_c[j * 2048 + r0 + 8];
                cd = f1 * cd + i1 * g1;
                g_c[j * 2048 + r0 + 8] = cd;
                Hn[j * 2048 + r0 + 8] = o1 * tanhf(cd);
            }
        }
    }
}

// ------------- per-step pos head + next-step front MLP -------------
__global__ void __launch_bounds__(256) posse(int s, const float* __restrict__ hp_w2,
                                             const float* __restrict__ hp_b2, float* outp) {
    __shared__ float w1s[8192];
    const float* hAn = g_hA[(s & 1) ^ 1];
    const float* lpc = g_lp[s & 1];
    float* lpn = g_lp[(s & 1) ^ 1];
    float* hAw = g_hA[(s & 1) ^ 1];
    int tid = threadIdx.x;
    for (int i = tid; i < 8192; i += 256) w1s[i] = g_hpw1f[i];
    __syncthreads();
    int w = tid >> 5, lane = tid & 31;
    int b = blockIdx.x * 32 + lane;
    float acc[16];
#pragma unroll
    for (int jj = 0; jj < 16; jj++) acc[jj] = 0.f;
    const float4* w4 = (const float4*)w1s;
    for (int jt = 0; jt < 64; jt++) {
        int j = w * 64 + jt;
        float hv = hAn[j * 2048 + b];
        float4 q0 = w4[j * 4], q1 = w4[j * 4 + 1], q2 = w4[j * 4 + 2], q3 = w4[j * 4 + 3];
        acc[0] += hv * q0.x; acc[1] += hv * q0.y; acc[2]  += hv * q0.z; acc[3]  += hv * q0.w;
        acc[4] += hv * q1.x; acc[5] += hv * q1.y; acc[6]  += hv * q1.z; acc[7]  += hv * q1.w;
        acc[8] += hv * q2.x; acc[9] += hv * q2.y; acc[10] += hv * q2.z; acc[11] += hv * q2.w;
        acc[12]+= hv * q3.x; acc[13]+= hv * q3.y; acc[14] += hv * q3.z; acc[15] += hv * q3.w;
    }
    __syncthreads();                 // done reading w1s; reuse as reduction buffer
    float* red = w1s;
#pragma unroll
    for (int jj = 0; jj < 16; jj++) red[(w * 32 + lane) * 17 + jj] = acc[jj];
    __syncthreads();
    if (tid < 32) {
        int bb = blockIdx.x * 32 + tid;
        float pr0 = hp_b2[0], pr1 = hp_b2[1];
#pragma unroll
        for (int jj = 0; jj < 16; jj++) {
            float v = g_hpb1f[jj];
#pragma unroll
            for (int ww = 0; ww < 8; ww++) v += red[(ww * 32 + tid) * 17 + jj];
            v = fmaxf(v, 0.f);
            pr0 += v * hp_w2[jj * 2];
            pr1 += v * hp_w2[jj * 2 + 1];
        }
        float l0 = lpc[bb * 2], l1 = lpc[bb * 2 + 1];
        float n0 = sigf(pr0 + l0), n1 = sigf(pr1 + l1);
        lpn[bb * 2] = n0; lpn[bb * 2 + 1] = n1;
        outp[bb * 2] = n0; outp[bb * 2 + 1] = n1;
        // hrelu for the NEXT step's A operand
#pragma unroll
        for (int jj = 0; jj < 16; jj++)
            hAw[(512 + jj) * 2048 + bb] =
                fmaxf(n0 * g_A1[jj] + n1 * g_A1[16 + jj] + g_B1[jj], 0.f);
    }
}

// ------------- launch -------------
extern "C" void kernel_launch(void* const* d_in, const int* in_sizes, int n_in,
                              void* d_out, int out_size) {
    const float* last_pos = (const float*)d_in[0];
    const float* hh    = (const float*)d_in[1];
    const float* ch    = (const float*)d_in[2];
    const float* se_w1 = (const float*)d_in[3];
    const float* se_b1 = (const float*)d_in[4];
    const float* se_g  = (const float*)d_in[5];
    const float* se_bt = (const float*)d_in[6];
    const float* se_m  = (const float*)d_in[7];
    const float* se_v  = (const float*)d_in[8];
    const float* se_w2 = (const float*)d_in[9];
    const float* se_b2 = (const float*)d_in[10];
    const float* w_ih  = (const float*)d_in[11];
    const float* w_hh  = (const float*)d_in[12];
    const float* b_ih  = (const float*)d_in[13];
    const float* b_hh  = (const float*)d_in[14];
    const float* hp_w1 = (const float*)d_in[15];
    const float* hp_b1 = (const float*)d_in[16];
    const float* hp_g  = (const float*)d_in[17];
    const float* hp_bt = (const float*)d_in[18];
    const float* hp_m  = (const float*)d_in[19];
    const float* hp_v  = (const float*)d_in[20];
    const float* hp_w2 = (const float*)d_in[21];
    const float* hp_b2 = (const float*)d_in[22];
    float* out = (float*)d_out;

    prep_fold<<<1, 256>>>(se_w1, se_b1, se_g, se_bt, se_m, se_v,
                          hp_w1, hp_b1, hp_g, hp_bt, hp_m, hp_v);
    prep_whh<<<4096, 256>>>(w_hh);
    prep_wse<<<128, 256>>>(se_w2, w_ih);
    prep_cb<<<8, 256>>>(se_b2, w_ih, b_ih, b_hh);
    init_hc<<<8192, 256>>>(hh, ch);
    init_front<<<8, 256>>>(last_pos);

    for (int s = 0; s < 32; s++) {
        gemm_lstm<<<dim3(16, 16), 256>>>(s & 1);
        posse<<<64, 256>>>(s, hp_w2, hp_b2, out + (size_t)s * 4096);
    }
}

// round 16
// speedup vs baseline: 1.0059x; 1.0059x over previous
#include <cuda_runtime.h>
#include <cuda_bf16.h>
#include <stdint.h>

#define BN_EPS 1e-5f
#define KTOT 528
#define NSTG 33   // KTOT / 16

// ------------- device scratch (no allocations allowed) -------------
__device__ float g_hA[2][KTOT * 2048];   // A operand, transposed [k][b]; rows 0..511 = h, 512..527 = hrelu
__device__ float g_c[512 * 2048];        // cell state transposed [j][b]
__device__ float g_lp[2][2048 * 2];
__device__ float g_Beff[KTOT * 2048];    // fused, tf32-rounded, cols n' = 4j+q
__device__ float g_cb[2048];             // fused gate bias
__device__ float g_A1[32];               // folded se layer1 weights [2][16]
__device__ float g_B1[16];
__device__ float g_hpw1f[8192];          // folded hp layer1 [512][16]
__device__ float g_hpb1f[16];

// ------------- helpers -------------
__device__ __forceinline__ float tf32rf(float x) {
    uint32_t u; asm("cvt.rna.tf32.f32 %0, %1;" : "=r"(u) : "f"(x));
    return __uint_as_float(u);
}
__device__ __forceinline__ uint32_t f2tf(float x) {
    uint32_t u; asm("cvt.rna.tf32.f32 %0, %1;" : "=r"(u) : "f"(x));
    return u;
}
__device__ __forceinline__ float sigf(float x) { return 1.f / (1.f + __expf(-x)); }

__device__ __forceinline__ void cp16(void* s, const void* g) {
    uint32_t sa = (uint32_t)__cvta_generic_to_shared(s);
    asm volatile("cp.async.cg.shared.global [%0], [%1], 16;\n" :: "r"(sa), "l"(g) : "memory");
}
__device__ __forceinline__ void mma8(float* c, const uint32_t* a, const uint32_t* b) {
    asm volatile(
        "mma.sync.aligned.m16n8k8.row.col.f32.tf32.tf32.f32 "
        "{%0,%1,%2,%3},{%4,%5,%6,%7},{%8,%9},{%0,%1,%2,%3};\n"
        : "+f"(c[0]), "+f"(c[1]), "+f"(c[2]), "+f"(c[3])
        : "r"(a[0]), "r"(a[1]), "r"(a[2]), "r"(a[3]), "r"(b[0]), "r"(b[1]));
}

// ------------- prep kernels (run once per launch, deterministic) -------------
__global__ void prep_fold(const float* se_w1, const float* se_b1, const float* se_g,
                          const float* se_bt, const float* se_m, const float* se_v,
                          const float* hp_w1, const float* hp_b1, const float* hp_g,
                          const float* hp_bt, const float* hp_m, const float* hp_v) {
    __shared__ float s2s[16];
    int t = threadIdx.x;
    if (t < 16) {
        float s = se_g[t] * rsqrtf(se_v[t] + BN_EPS);
        g_A1[t]      = se_w1[t] * s;
        g_A1[16 + t] = se_w1[16 + t] * s;
        g_B1[t]      = (se_b1[t] - se_m[t]) * s + se_bt[t];
        float s2 = hp_g[t] * rsqrtf(hp_v[t] + BN_EPS);
        s2s[t] = s2;
        g_hpb1f[t] = (hp_b1[t] - hp_m[t]) * s2 + hp_bt[t];
    }
    __syncthreads();
    for (int i = t; i < 8192; i += 256) g_hpw1f[i] = hp_w1[i] * s2s[i & 15];
}

// Beff rows 0..511: interleaved w_hh transpose
__global__ void prep_whh(const float* __restrict__ w_hh) {
    int id = blockIdx.x * 256 + threadIdx.x;          // 1048576 threads
    int np = id & 2047, k = id >> 11;
    int j = np >> 2, q = np & 3;
    g_Beff[k * 2048 + np] = tf32rf(w_hh[(q * 512 + j) * 512 + k]);
}

// Beff rows 512..527: Wse[jj][n] = sum_e se_w2[jj][e] * w_ih[n][e]
__global__ void prep_wse(const float* __restrict__ se_w2, const float* __restrict__ w_ih) {
    int id = blockIdx.x * 256 + threadIdx.x;          // 32768 threads
    int jj = id & 15, np = id >> 4;
    int j = np >> 2, q = np & 3;
    const float4* wr = (const float4*)(w_ih + (size_t)(q * 512 + j) * 512);
    const float4* sw = (const float4*)(se_w2 + (size_t)jj * 512);
    float acc = 0.f;
#pragma unroll 4
    for (int e = 0; e < 128; e++) {
        float4 a = wr[e], b = sw[e];
        acc += a.x * b.x + a.y * b.y + a.z * b.z + a.w * b.w;
    }
    g_Beff[(512 + jj) * 2048 + np] = tf32rf(acc);
}

// fused bias cb[n'] = b_ih[n] + b_hh[n] + se_b2 . w_ih[n]
__global__ void prep_cb(const float* __restrict__ se_b2, const float* __restrict__ w_ih,
                        const float* __restrict__ b_ih, const float* __restrict__ b_hh) {
    int np = blockIdx.x * 256 + threadIdx.x;          // 2048 threads
    int j = np >> 2, q = np & 3;
    int n = q * 512 + j;
    const float4* wr = (const float4*)(w_ih + (size_t)n * 512);
    const float4* sb = (const float4*)se_b2;
    float acc = b_ih[n] + b_hh[n];
#pragma unroll 4
    for (int e = 0; e < 128; e++) {
        float4 a = wr[e], b = sb[e];
        acc += a.x * b.x + a.y * b.y + a.z * b.z + a.w * b.w;
    }
    g_cb[np] = acc;
}

// transpose h0 -> g_hA[0], c0 -> g_c
__global__ void init_hc(const float* __restrict__ hh, const float* __restrict__ ch) {
    int id = blockIdx.x * 256 + threadIdx.x;          // 2097152 threads
    if (id < 1048576) {
        int b = id & 2047, j = id >> 11;
        g_hA[0][j * 2048 + b] = hh[b * 512 + j];
    } else {
        int k = id - 1048576;
        int b = k & 2047, j = k >> 11;
        g_c[j * 2048 + b] = ch[b * 512 + j];
    }
}

// lp0 copy + hrelu(lp0) into g_hA[0] rows 512..527  (needs prep_fold first)
__global__ void init_front(const float* __restrict__ last_pos) {
    int b = blockIdx.x * 256 + threadIdx.x;           // 2048 threads
    float l0 = last_pos[b * 2], l1 = last_pos[b * 2 + 1];
    g_lp[0][b * 2] = l0; g_lp[0][b * 2 + 1] = l1;
#pragma unroll
    for (int jj = 0; jj < 16; jj++)
        g_hA[0][(512 + jj) * 2048 + b] =
            fmaxf(l0 * g_A1[jj] + l1 * g_A1[16 + jj] + g_B1[jj], 0.f);
}

// ------------- per-step GEMM + fused LSTM cell -------------
// gates[b][n'] = sum_k A[k][b] * Beff[k][n'] + cb[n']; in-register i,f,g,o combine via lane^1 shfl.
__global__ void __launch_bounds__(256, 2) gemm_lstm(int cur) {
    __shared__ __align__(16) float As[2][16][132];
    __shared__ __align__(16) float Bs[2][16][132];
    const float* Ag = g_hA[cur];
    float* Hn = g_hA[cur ^ 1];
    int tid = threadIdx.x;
    int bm = blockIdx.y * 128, bn = blockIdx.x * 128;
    int lane = tid & 31, wid = tid >> 5;
    int wm = wid & 3, wn = wid >> 2;      // 4 warps in M (32 rows), 2 in N (64 cols)
    int tig = lane & 3, grp = lane >> 2;

    float acc[2][8][4];
#pragma unroll
    for (int a = 0; a < 2; a++)
#pragma unroll
        for (int b = 0; b < 8; b++)
#pragma unroll
            for (int c = 0; c < 4; c++) acc[a][b][c] = 0.f;

    auto load = [&](int st, int buf) {
        int k0 = st * 16;
#pragma unroll
        for (int i = 0; i < 2; i++) {
            int c = tid + i * 256;
            int row = c >> 5, ch = c & 31;
            cp16(&As[buf][row][ch * 4], Ag + (size_t)(k0 + row) * 2048 + bm + ch * 4);
            cp16(&Bs[buf][row][ch * 4], g_Beff + (size_t)(k0 + row) * 2048 + bn + ch * 4);
        }
    };

    load(0, 0);
    asm volatile("cp.async.commit_group;\n" ::: "memory");
    int buf = 0;
    for (int st = 0; st < NSTG; st++) {
        if (st + 1 < NSTG) load(st + 1, buf ^ 1);
        asm volatile("cp.async.commit_group;\n" ::: "memory");
        asm volatile("cp.async.wait_group 1;\n" ::: "memory");
        __syncthreads();
#pragma unroll
        for (int k8 = 0; k8 < 16; k8 += 8) {
            uint32_t af[2][4], bf[8][2];
#pragma unroll
            for (int mt = 0; mt < 2; mt++) {
                int m0 = wm * 32 + mt * 16 + grp;
                af[mt][0] = f2tf(As[buf][k8 + tig][m0]);
                af[mt][1] = f2tf(As[buf][k8 + tig][m0 + 8]);
                af[mt][2] = f2tf(As[buf][k8 + tig + 4][m0]);
                af[mt][3] = f2tf(As[buf][k8 + tig + 4][m0 + 8]);
            }
#pragma unroll
            for (int nt = 0; nt < 8; nt++) {
                int n0 = wn * 64 + nt * 8 + grp;
                bf[nt][0] = __float_as_uint(Bs[buf][k8 + tig][n0]);
                bf[nt][1] = __float_as_uint(Bs[buf][k8 + tig + 4][n0]);
            }
#pragma unroll
            for (int mt = 0; mt < 2; mt++)
#pragma unroll
                for (int nt = 0; nt < 8; nt++) mma8(acc[mt][nt], af[mt], bf[nt]);
        }
        __syncthreads();
        buf ^= 1;
    }

    // epilogue: lane pairs hold (i,f) / (g,o) of the same unit j
#pragma unroll
    for (int mt = 0; mt < 2; mt++) {
        int r0 = bm + wm * 32 + mt * 16 + grp;
#pragma unroll
        for (int nt = 0; nt < 8; nt++) {
            int col = bn + wn * 64 + nt * 8 + 2 * tig;
            float cb0 = g_cb[col], cb1 = g_cb[col + 1];
            float c0 = acc[mt][nt][0] + cb0;
            float c1 = acc[mt][nt][1] + cb1;
            float c2 = acc[mt][nt][2] + cb0;
            float c3 = acc[mt][nt][3] + cb1;
            float p0 = __shfl_xor_sync(0xffffffffu, c0, 1);
            float p1 = __shfl_xor_sync(0xffffffffu, c1, 1);
            float p2 = __shfl_xor_sync(0xffffffffu, c2, 1);
            float p3 = __shfl_xor_sync(0xffffffffu, c3, 1);
            if (!(lane & 1)) {                 // even lane: owns (i,f), partner sent (g,o)
                int j = col >> 2;
                float i0 = sigf(c0), f0 = sigf(c1), g0 = tanhf(p0), o0 = sigf(p1);
                float cc = g_c[j * 2048 + r0];
                cc = f0 * cc + i0 * g0;
                g_c[j * 2048 + r0] = cc;
                Hn[j * 2048 + r0] = o0 * tanhf(cc);
                float i1 = sigf(c2), f1 = sigf(c3), g1 = tanhf(p2), o1 = sigf(p3);
                float cd = g_c[j * 2048 + r0 + 8];
                cd = f1 * cd + i1 * g1;
                g_c[j * 2048 + r0 + 8] = cd;
                Hn[j * 2048 + r0 + 8] = o1 * tanhf(cd);
            }
        }
    }
}

// ------------- per-step pos head + next-step front MLP -------------
__global__ void __launch_bounds__(256) posse(int s, const float* __restrict__ hp_w2,
                                             const float* __restrict__ hp_b2, float* outp) {
    __shared__ float w1s[8192];
    const float* hAn = g_hA[(s & 1) ^ 1];
    const float* lpc = g_lp[s & 1];
    float* lpn = g_lp[(s & 1) ^ 1];
    float* hAw = g_hA[(s & 1) ^ 1];
    int tid = threadIdx.x;
    for (int i = tid; i < 8192; i += 256) w1s[i] = g_hpw1f[i];
    __syncthreads();
    int w = tid >> 5, lane = tid & 31;
    int b = blockIdx.x * 32 + lane;
    float acc[16];
#pragma unroll
    for (int jj = 0; jj < 16; jj++) acc[jj] = 0.f;
    const float4* w4 = (const float4*)w1s;
    for (int jt = 0; jt < 64; jt++) {
        int j = w * 64 + jt;
        float hv = hAn[j * 2048 + b];
        float4 q0 = w4[j * 4], q1 = w4[j * 4 + 1], q2 = w4[j * 4 + 2], q3 = w4[j * 4 + 3];
        acc[0] += hv * q0.x; acc[1] += hv * q0.y; acc[2]  += hv * q0.z; acc[3]  += hv * q0.w;
        acc[4] += hv * q1.x; acc[5] += hv * q1.y; acc[6]  += hv * q1.z; acc[7]  += hv * q1.w;
        acc[8] += hv * q2.x; acc[9] += hv * q2.y; acc[10] += hv * q2.z; acc[11] += hv * q2.w;
        acc[12]+= hv * q3.x; acc[13]+= hv * q3.y; acc[14] += hv * q3.z; acc[15] += hv * q3.w;
    }
    __syncthreads();                 // done reading w1s; reuse as reduction buffer
    float* red = w1s;
#pragma unroll
    for (int jj = 0; jj < 16; jj++) red[(w * 32 + lane) * 17 + jj] = acc[jj];
    __syncthreads();
    if (tid < 32) {
        int bb = blockIdx.x * 32 + tid;
        float pr0 = hp_b2[0], pr1 = hp_b2[1];
#pragma unroll
        for (int jj = 0; jj < 16; jj++) {
            float v = g_hpb1f[jj];
#pragma unroll
            for (int ww = 0; ww < 8; ww++) v += red[(ww * 32 + tid) * 17 + jj];
            v = fmaxf(v, 0.f);
            pr0 += v * hp_w2[jj * 2];
            pr1 += v * hp_w2[jj * 2 + 1];
        }
        float l0 = lpc[bb * 2], l1 = lpc[bb * 2 + 1];
        float n0 = sigf(pr0 + l0), n1 = sigf(pr1 + l1);
        lpn[bb * 2] = n0; lpn[bb * 2 + 1] = n1;
        outp[bb * 2] = n0; outp[bb * 2 + 1] = n1;
        // hrelu for the NEXT step's A operand
#pragma unroll
        for (int jj = 0; jj < 16; jj++)
            hAw[(512 + jj) * 2048 + bb] =
                fmaxf(n0 * g_A1[jj] + n1 * g_A1[16 + jj] + g_B1[jj], 0.f);
    }
}

// ------------- launch -------------
extern "C" void kernel_launch(void* const* d_in, const int* in_sizes, int n_in,
                              void* d_out, int out_size) {
    const float* last_pos = (const float*)d_in[0];
    const float* hh    = (const float*)d_in[1];
    const float* ch    = (const float*)d_in[2];
    const float* se_w1 = (const float*)d_in[3];
    const float* se_b1 = (const float*)d_in[4];
    const float* se_g  = (const float*)d_in[5];
    const float* se_bt = (const float*)d_in[6];
    const float* se_m  = (const float*)d_in[7];
    const float* se_v  = (const float*)d_in[8];
    const float* se_w2 = (const float*)d_in[9];
    const float* se_b2 = (const float*)d_in[10];
    const float* w_ih  = (const float*)d_in[11];
    const float* w_hh  = (const float*)d_in[12];
    const float* b_ih  = (const float*)d_in[13];
    const float* b_hh  = (const float*)d_in[14];
    const float* hp_w1 = (const float*)d_in[15];
    const float* hp_b1 = (const float*)d_in[16];
    const float* hp_g  = (const float*)d_in[17];
    const float* hp_bt = (const float*)d_in[18];
    const float* hp_m  = (const float*)d_in[19];
    const float* hp_v  = (const float*)d_in[20];
    const float* hp_w2 = (const float*)d_in[21];
    const float* hp_b2 = (const float*)d_in[22];
    float* out = (float*)d_out;

    prep_fold<<<1, 256>>>(se_w1, se_b1, se_g, se_bt, se_m, se_v,
                          hp_w1, hp_b1, hp_g, hp_bt, hp_m, hp_v);
    prep_whh<<<4096, 256>>>(w_hh);
    prep_wse<<<128, 256>>>(se_w2, w_ih);
    prep_cb<<<8, 256>>>(se_b2, w_ih, b_ih, b_hh);
    init_hc<<<8192, 256>>>(hh, ch);
    init_front<<<8, 256>>>(last_pos);

    for (int s = 0; s < 32; s++) {
        gemm_lstm<<<dim3(16, 16), 256>>>(s & 1);
        posse<<<64, 256>>>(s, hp_w2, hp_b2, out + (size_t)s * 4096);
    }
}